// round 4
// baseline (speedup 1.0000x reference)
#include <cuda_runtime.h>
#include <cuda_bf16.h>
#include <cstdint>

// QFNetBlock: normalize -> 4 complex GEMM layers (CNOT perm after 0,2) -> abs.
// B=256, D=4096. Complex GEMM via mma.sync bf16 (hi/lo split x3, fp32 accum),
// Karatsuba (3 real products), double-buffered smem, ldmatrix fragment loads.

#define DD 4096
#define BB 256
#define NW 12

#define KC 16
#define NCHUNK (DD / KC)   // 256
#define SROW 24            // bf16 per smem row (48 B)
#define SROWB 48           // bytes per smem row

// tile row offsets within one buffer (rows of SROW bf16)
#define T_SRH 0
#define T_SRL 64
#define T_SIH 128
#define T_SIL 192
#define T_SSH 256
#define T_SSL 320
#define T_URH 384
#define T_URL 512
#define T_UIH 640
#define T_UIL 768
#define T_USH 896
#define T_USL 1024
#define BUF_ROWS 1152
#define BUF_ELEMS (BUF_ROWS * SROW)             // 27648 bf16
#define SMEM_BYTES (2 * BUF_ELEMS * 2)          // 110592 B

// Ping-pong complex state scratch (4 MB each).
__device__ float g_r0[BB * DD];
__device__ float g_i0[BB * DD];
__device__ float g_r1[BB * DD];
__device__ float g_i1[BB * DD];

__device__ __forceinline__ uint32_t smem_u32(const void* p) {
    uint32_t a;
    asm("{ .reg .u64 t; cvta.to.shared.u64 t, %1; cvt.u32.u64 %0, t; }" : "=r"(a) : "l"(p));
    return a;
}

__device__ __forceinline__ void cvt_hilo2(float a, float b, uint32_t& hi, uint32_t& lo) {
    __nv_bfloat16 ha = __float2bfloat16_rn(a);
    __nv_bfloat16 hb = __float2bfloat16_rn(b);
    __nv_bfloat16 la = __float2bfloat16_rn(a - __bfloat162float(ha));
    __nv_bfloat16 lb = __float2bfloat16_rn(b - __bfloat162float(hb));
    __nv_bfloat162 h2 = __halves2bfloat162(ha, hb);
    __nv_bfloat162 l2 = __halves2bfloat162(la, lb);
    hi = *reinterpret_cast<uint32_t*>(&h2);
    lo = *reinterpret_cast<uint32_t*>(&l2);
}

__device__ __forceinline__ void store_hilo(__nv_bfloat16* bufH, __nv_bfloat16* bufL,
                                           int row, int kp, float4 v) {
    uint32_t h0, l0, h1, l1;
    cvt_hilo2(v.x, v.y, h0, l0);
    cvt_hilo2(v.z, v.w, h1, l1);
    *reinterpret_cast<uint2*>(bufH + row * SROW + kp) = make_uint2(h0, h1);
    *reinterpret_cast<uint2*>(bufL + row * SROW + kp) = make_uint2(l0, l1);
}

__device__ __forceinline__ void ldm4(uint32_t* r, uint32_t addr) {
    asm volatile("ldmatrix.sync.aligned.m8n8.x4.shared.b16 {%0,%1,%2,%3}, [%4];"
                 : "=r"(r[0]), "=r"(r[1]), "=r"(r[2]), "=r"(r[3]) : "r"(addr));
}

#define MMA(C, A, B)                                                           \
    asm volatile(                                                              \
        "mma.sync.aligned.m16n8k16.row.col.f32.bf16.bf16.f32 "                 \
        "{%0,%1,%2,%3}, {%4,%5,%6,%7}, {%8,%9}, {%0,%1,%2,%3};"                \
        : "+f"((C)[0]), "+f"((C)[1]), "+f"((C)[2]), "+f"((C)[3])               \
        : "r"((A)[0]), "r"((A)[1]), "r"((A)[2]), "r"((A)[3]),                  \
          "r"((B)[0]), "r"((B)[1]))

// ---------------------------------------------------------------------------
// Complex GEMM: O[b,i] = sum_k U[i,k] * S[b,k]  (complex)
// CTA tile M=64 (batch) x N=128 (i). 8 warps 2x4, warp tile 32x32.
// Karatsuba: P1=Ur*Sr, P2=Ui*Si, P3=(Ur+Ui)(Sr+Si); Re=P1-P2, Im=P3-P1-P2.
// CPLX=false (Si=0): P1=Ur*Sr -> Re, P2=Ui*Sr -> Im.
// ---------------------------------------------------------------------------
template <bool CPLX>
__global__ void __launch_bounds__(256, 1)
cgemm_mma(const float* __restrict__ Ur, const float* __restrict__ Ui,
          const float* __restrict__ Sr, const float* __restrict__ Si,
          float* __restrict__ Or, float* __restrict__ Oi) {
    extern __shared__ __align__(16) __nv_bfloat16 sm[];

    const int tid = threadIdx.x;
    const int wid = tid >> 5;
    const int lane = tid & 31;
    const int ibase = blockIdx.x * 128;
    const int bbase = blockIdx.y * 64;

    // loader mapping
    const int arow = tid >> 2;
    const int akp = (tid & 3) << 2;
    const float* pSr = Sr + (size_t)(bbase + arow) * DD + akp;
    const float* pSi = Si + (size_t)(bbase + arow) * DD + akp;
    const float* pUr0 = Ur + (size_t)(ibase + arow) * DD + akp;
    const float* pUr1 = Ur + (size_t)(ibase + arow + 64) * DD + akp;
    const float* pUi0 = Ui + (size_t)(ibase + arow) * DD + akp;
    const float* pUi1 = Ui + (size_t)(ibase + arow + 64) * DD + akp;

    // compute mapping
    const int warp_m = wid & 1;
    const int warp_n = wid >> 1;
    const int lrow = lane >> 2;
    const int lcol2 = (lane & 3) << 1;

    // ldmatrix per-lane byte offsets
    const uint32_t aLane = (uint32_t)((lane & 15) * SROWB + (lane >> 4) * 16);
    const uint32_t bLane = (uint32_t)((((lane >> 4) << 3) + (lane & 7)) * SROWB +
                                      ((lane >> 3) & 1) * 16);
    const uint32_t smbase = smem_u32(sm);

    float cP1[2][4][4], cP2[2][4][4], cP3[2][4][4];
#pragma unroll
    for (int m = 0; m < 2; ++m)
#pragma unroll
        for (int n = 0; n < 4; ++n)
#pragma unroll
            for (int r = 0; r < 4; ++r) {
                cP1[m][n][r] = 0.f; cP2[m][n][r] = 0.f; cP3[m][n][r] = 0.f;
            }

    // stage one chunk into buffer buf
    auto stage = [&](int buf, float4 sr, float4 si, float4 ur0, float4 ur1,
                     float4 ui0, float4 ui1) {
        __nv_bfloat16* B = sm + buf * BUF_ELEMS;
        store_hilo(B + T_SRH * SROW, B + T_SRL * SROW, arow, akp, sr);
        store_hilo(B + T_URH * SROW, B + T_URL * SROW, arow, akp, ur0);
        store_hilo(B + T_URH * SROW, B + T_URL * SROW, arow + 64, akp, ur1);
        store_hilo(B + T_UIH * SROW, B + T_UIL * SROW, arow, akp, ui0);
        store_hilo(B + T_UIH * SROW, B + T_UIL * SROW, arow + 64, akp, ui1);
        if (CPLX) {
            store_hilo(B + T_SIH * SROW, B + T_SIL * SROW, arow, akp, si);
            float4 ss = make_float4(sr.x + si.x, sr.y + si.y, sr.z + si.z, sr.w + si.w);
            store_hilo(B + T_SSH * SROW, B + T_SSL * SROW, arow, akp, ss);
            float4 us0 = make_float4(ur0.x + ui0.x, ur0.y + ui0.y, ur0.z + ui0.z, ur0.w + ui0.w);
            float4 us1 = make_float4(ur1.x + ui1.x, ur1.y + ui1.y, ur1.z + ui1.z, ur1.w + ui1.w);
            store_hilo(B + T_USH * SROW, B + T_USL * SROW, arow, akp, us0);
            store_hilo(B + T_USH * SROW, B + T_USL * SROW, arow + 64, akp, us1);
        }
    };

    // prologue: chunk 0 -> buf 0, prefetch chunk 1 into regs
    float4 v_sr = *reinterpret_cast<const float4*>(pSr);
    float4 v_si = CPLX ? *reinterpret_cast<const float4*>(pSi) : make_float4(0, 0, 0, 0);
    float4 v_ur0 = *reinterpret_cast<const float4*>(pUr0);
    float4 v_ur1 = *reinterpret_cast<const float4*>(pUr1);
    float4 v_ui0 = *reinterpret_cast<const float4*>(pUi0);
    float4 v_ui1 = *reinterpret_cast<const float4*>(pUi1);
    stage(0, v_sr, v_si, v_ur0, v_ur1, v_ui0, v_ui1);
    {
        v_sr = *reinterpret_cast<const float4*>(pSr + KC);
        if (CPLX) v_si = *reinterpret_cast<const float4*>(pSi + KC);
        v_ur0 = *reinterpret_cast<const float4*>(pUr0 + KC);
        v_ur1 = *reinterpret_cast<const float4*>(pUr1 + KC);
        v_ui0 = *reinterpret_cast<const float4*>(pUi0 + KC);
        v_ui1 = *reinterpret_cast<const float4*>(pUi1 + KC);
    }
    __syncthreads();

#pragma unroll 1
    for (int c = 0; c < NCHUNK; ++c) {
        // stage chunk c+1 into the other buffer
        if (c + 1 < NCHUNK)
            stage((c + 1) & 1, v_sr, v_si, v_ur0, v_ur1, v_ui0, v_ui1);
        // prefetch chunk c+2
        if (c + 2 < NCHUNK) {
            const int off = (c + 2) * KC;
            v_sr = *reinterpret_cast<const float4*>(pSr + off);
            if (CPLX) v_si = *reinterpret_cast<const float4*>(pSi + off);
            v_ur0 = *reinterpret_cast<const float4*>(pUr0 + off);
            v_ur1 = *reinterpret_cast<const float4*>(pUr1 + off);
            v_ui0 = *reinterpret_cast<const float4*>(pUi0 + off);
            v_ui1 = *reinterpret_cast<const float4*>(pUi1 + off);
        }

        // MMA phase on buffer c&1
        const uint32_t base = smbase + (uint32_t)((c & 1) * BUF_ELEMS * 2);
#pragma unroll
        for (int m = 0; m < 2; ++m) {
            const uint32_t am = base + aLane + (uint32_t)((warp_m * 32 + m * 16) * SROWB);
            uint32_t aSrH[4], aSrL[4], aSiH[4], aSiL[4], aSsH[4], aSsL[4];
            ldm4(aSrH, am + T_SRH * SROWB);
            ldm4(aSrL, am + T_SRL * SROWB);
            if (CPLX) {
                ldm4(aSiH, am + T_SIH * SROWB);
                ldm4(aSiL, am + T_SIL * SROWB);
                ldm4(aSsH, am + T_SSH * SROWB);
                ldm4(aSsL, am + T_SSL * SROWB);
            }
#pragma unroll
            for (int np = 0; np < 2; ++np) {
                const uint32_t bm = base + bLane + (uint32_t)((warp_n * 32 + np * 16) * SROWB);
                uint32_t bUrH[4], bUrL[4], bUiH[4], bUiL[4], bUsH[4], bUsL[4];
                ldm4(bUrH, bm + T_URH * SROWB);
                ldm4(bUrL, bm + T_URL * SROWB);
                ldm4(bUiH, bm + T_UIH * SROWB);
                ldm4(bUiL, bm + T_UIL * SROWB);
                if (CPLX) {
                    ldm4(bUsH, bm + T_USH * SROWB);
                    ldm4(bUsL, bm + T_USL * SROWB);
                }
                const int n0 = np * 2, n1 = np * 2 + 1;
                // P1 = Sr * Ur (hh, lh, hl)
                MMA(cP1[m][n0], aSrH, bUrH + 0);
                MMA(cP1[m][n0], aSrL, bUrH + 0);
                MMA(cP1[m][n0], aSrH, bUrL + 0);
                MMA(cP1[m][n1], aSrH, bUrH + 2);
                MMA(cP1[m][n1], aSrL, bUrH + 2);
                MMA(cP1[m][n1], aSrH, bUrL + 2);
                if (CPLX) {
                    // P2 = Si * Ui
                    MMA(cP2[m][n0], aSiH, bUiH + 0);
                    MMA(cP2[m][n0], aSiL, bUiH + 0);
                    MMA(cP2[m][n0], aSiH, bUiL + 0);
                    MMA(cP2[m][n1], aSiH, bUiH + 2);
                    MMA(cP2[m][n1], aSiL, bUiH + 2);
                    MMA(cP2[m][n1], aSiH, bUiL + 2);
                    // P3 = Ss * Us
                    MMA(cP3[m][n0], aSsH, bUsH + 0);
                    MMA(cP3[m][n0], aSsL, bUsH + 0);
                    MMA(cP3[m][n0], aSsH, bUsL + 0);
                    MMA(cP3[m][n1], aSsH, bUsH + 2);
                    MMA(cP3[m][n1], aSsL, bUsH + 2);
                    MMA(cP3[m][n1], aSsH, bUsL + 2);
                } else {
                    // P2 = Sr * Ui  (imag part for real input)
                    MMA(cP2[m][n0], aSrH, bUiH + 0);
                    MMA(cP2[m][n0], aSrL, bUiH + 0);
                    MMA(cP2[m][n0], aSrH, bUiL + 0);
                    MMA(cP2[m][n1], aSrH, bUiH + 2);
                    MMA(cP2[m][n1], aSrL, bUiH + 2);
                    MMA(cP2[m][n1], aSrH, bUiL + 2);
                }
            }
        }
        __syncthreads();
    }

    // epilogue
#pragma unroll
    for (int m = 0; m < 2; ++m) {
#pragma unroll
        for (int n = 0; n < 4; ++n) {
            float oR[4], oI[4];
#pragma unroll
            for (int r = 0; r < 4; ++r) {
                if (CPLX) {
                    oR[r] = cP1[m][n][r] - cP2[m][n][r];
                    oI[r] = cP3[m][n][r] - cP1[m][n][r] - cP2[m][n][r];
                } else {
                    oR[r] = cP1[m][n][r];
                    oI[r] = cP2[m][n][r];
                }
            }
            const int brow = bbase + warp_m * 32 + m * 16 + lrow;
            const int icol = ibase + warp_n * 32 + n * 8 + lcol2;
            *reinterpret_cast<float2*>(Or + (size_t)brow * DD + icol) =
                make_float2(oR[0], oR[1]);
            *reinterpret_cast<float2*>(Or + (size_t)(brow + 8) * DD + icol) =
                make_float2(oR[2], oR[3]);
            *reinterpret_cast<float2*>(Oi + (size_t)brow * DD + icol) =
                make_float2(oI[0], oI[1]);
            *reinterpret_cast<float2*>(Oi + (size_t)(brow + 8) * DD + icol) =
                make_float2(oI[2], oI[3]);
        }
    }
}

// ---------------------------------------------------------------------------
__global__ void normalize_kernel(const float* __restrict__ x, float* __restrict__ sr) {
    const int b = blockIdx.x;
    const float4* xv = reinterpret_cast<const float4*>(x + (size_t)b * DD);
    float ss = 0.f;
#pragma unroll 4
    for (int i = threadIdx.x; i < DD / 4; i += blockDim.x) {
        float4 v = xv[i];
        ss += v.x * v.x + v.y * v.y + v.z * v.z + v.w * v.w;
    }
    __shared__ float red[256];
    red[threadIdx.x] = ss;
    __syncthreads();
    for (int s = 128; s > 0; s >>= 1) {
        if (threadIdx.x < s) red[threadIdx.x] += red[threadIdx.x + s];
        __syncthreads();
    }
    const float inv = rsqrtf(red[0]);
    float4* ov = reinterpret_cast<float4*>(sr + (size_t)b * DD);
    for (int i = threadIdx.x; i < DD / 4; i += blockDim.x) {
        float4 v = xv[i];
        v.x *= inv; v.y *= inv; v.z *= inv; v.w *= inv;
        ov[i] = v;
    }
}

__global__ void perm_kernel(const float* __restrict__ inr, const float* __restrict__ ini,
                            float* __restrict__ outr, float* __restrict__ outi) {
    const int idx = blockIdx.x * blockDim.x + threadIdx.x;
    const int b = idx >> 12;
    const int j = idx & (DD - 1);
    int m = j;
#pragma unroll
    for (int i = NW - 1; i >= 0; --i) {
        const int cc = NW - 1 - i;
        const int t = NW - 1 - ((i + 1) % NW);
        m ^= ((m >> cc) & 1) << t;
    }
    const size_t src = ((size_t)b << 12) + m;
    outr[idx] = inr[src];
    outi[idx] = ini[src];
}

__global__ void abs_kernel(const float* __restrict__ re, const float* __restrict__ im,
                           float* __restrict__ out) {
    const int idx = blockIdx.x * blockDim.x + threadIdx.x;
    const float r = re[idx];
    const float i = im[idx];
    out[idx] = sqrtf(r * r + i * i);
}

// ---------------------------------------------------------------------------
extern "C" void kernel_launch(void* const* d_in, const int* in_sizes, int n_in,
                              void* d_out, int out_size) {
    const float* x   = (const float*)d_in[0];
    const float* u0r = (const float*)d_in[1];
    const float* u0i = (const float*)d_in[2];
    const float* u1r = (const float*)d_in[3];
    const float* u1i = (const float*)d_in[4];
    const float* u2r = (const float*)d_in[5];
    const float* u2i = (const float*)d_in[6];
    const float* u3r = (const float*)d_in[7];
    const float* u3i = (const float*)d_in[8];
    float* out = (float*)d_out;

    cudaFuncSetAttribute(cgemm_mma<true>, cudaFuncAttributeMaxDynamicSharedMemorySize,
                         SMEM_BYTES);
    cudaFuncSetAttribute(cgemm_mma<false>, cudaFuncAttributeMaxDynamicSharedMemorySize,
                         SMEM_BYTES);

    float *r0, *i0, *r1, *i1;
    cudaGetSymbolAddress((void**)&r0, g_r0);
    cudaGetSymbolAddress((void**)&i0, g_i0);
    cudaGetSymbolAddress((void**)&r1, g_r1);
    cudaGetSymbolAddress((void**)&i1, g_i1);

    const dim3 gg(DD / 128, BB / 64);  // (32, 4) = 128 CTAs
    const int elems = BB * DD;

    normalize_kernel<<<BB, 256>>>(x, r0);
    cgemm_mma<false><<<gg, 256, SMEM_BYTES>>>(u0r, u0i, r0, r0, r1, i1);
    perm_kernel<<<elems / 256, 256>>>(r1, i1, r0, i0);
    cgemm_mma<true><<<gg, 256, SMEM_BYTES>>>(u1r, u1i, r0, i0, r1, i1);
    cgemm_mma<true><<<gg, 256, SMEM_BYTES>>>(u2r, u2i, r1, i1, r0, i0);
    perm_kernel<<<elems / 256, 256>>>(r0, i0, r1, i1);
    cgemm_mma<true><<<gg, 256, SMEM_BYTES>>>(u3r, u3i, r1, i1, r0, i0);
    abs_kernel<<<elems / 256, 256>>>(r0, i0, out);
}

// round 5
// speedup vs baseline: 1.0038x; 1.0038x over previous
#include <cuda_runtime.h>
#include <cuda_bf16.h>
#include <cstdint>

// QFNetBlock: normalize -> 4 complex GEMM layers (CNOT perm after 0,2) -> abs.
// Complex GEMM via mma.sync bf16 (hi/lo 3-term split, fp32 accum), 512 threads,
// double-buffered smem, ldmatrix fragment loads, negated-Si for the subtraction.

#define DD 4096
#define BB 256
#define NW 12

#define KC 16
#define NCHUNK (DD / KC)   // 256
#define SROW 24            // bf16 per smem row (48 B)
#define SROWB 48

// tile row offsets within one buffer (units: rows of SROW bf16)
#define T_SRH 0
#define T_SRL 64
#define T_SIH 128
#define T_SIL 192
#define T_URH 256
#define T_URL 384
#define T_UIH 512
#define T_UIL 640
#define BUF_ROWS 768
#define BUF_ELEMS (BUF_ROWS * SROW)      // 18432 bf16 = 36864 B
#define SMEM_BYTES (2 * BUF_ELEMS * 2)   // 73728 B

// Ping-pong complex state scratch (4 MB each).
__device__ float g_r0[BB * DD];
__device__ float g_i0[BB * DD];
__device__ float g_r1[BB * DD];
__device__ float g_i1[BB * DD];

__device__ __forceinline__ uint32_t smem_u32(const void* p) {
    uint32_t a;
    asm("{ .reg .u64 t; cvta.to.shared.u64 t, %1; cvt.u32.u64 %0, t; }" : "=r"(a) : "l"(p));
    return a;
}

__device__ __forceinline__ void cvt_hilo2(float a, float b, uint32_t& hi, uint32_t& lo) {
    __nv_bfloat16 ha = __float2bfloat16_rn(a);
    __nv_bfloat16 hb = __float2bfloat16_rn(b);
    __nv_bfloat16 la = __float2bfloat16_rn(a - __bfloat162float(ha));
    __nv_bfloat16 lb = __float2bfloat16_rn(b - __bfloat162float(hb));
    __nv_bfloat162 h2 = __halves2bfloat162(ha, hb);
    __nv_bfloat162 l2 = __halves2bfloat162(la, lb);
    hi = *reinterpret_cast<uint32_t*>(&h2);
    lo = *reinterpret_cast<uint32_t*>(&l2);
}

__device__ __forceinline__ void store_hilo(__nv_bfloat16* bufH, __nv_bfloat16* bufL,
                                           int row, int kp, float4 v) {
    uint32_t h0, l0, h1, l1;
    cvt_hilo2(v.x, v.y, h0, l0);
    cvt_hilo2(v.z, v.w, h1, l1);
    *reinterpret_cast<uint2*>(bufH + row * SROW + kp) = make_uint2(h0, h1);
    *reinterpret_cast<uint2*>(bufL + row * SROW + kp) = make_uint2(l0, l1);
}

__device__ __forceinline__ void ldm4(uint32_t* r, uint32_t addr) {
    asm volatile("ldmatrix.sync.aligned.m8n8.x4.shared.b16 {%0,%1,%2,%3}, [%4];"
                 : "=r"(r[0]), "=r"(r[1]), "=r"(r[2]), "=r"(r[3]) : "r"(addr));
}

#define MMA(C, A, B)                                                           \
    asm volatile(                                                              \
        "mma.sync.aligned.m16n8k16.row.col.f32.bf16.bf16.f32 "                 \
        "{%0,%1,%2,%3}, {%4,%5,%6,%7}, {%8,%9}, {%0,%1,%2,%3};"                \
        : "+f"((C)[0]), "+f"((C)[1]), "+f"((C)[2]), "+f"((C)[3])               \
        : "r"((A)[0]), "r"((A)[1]), "r"((A)[2]), "r"((A)[3]),                  \
          "r"((B)[0]), "r"((B)[1]))

// ---------------------------------------------------------------------------
// Complex GEMM: O[b,i] = sum_k U[i,k] * S[b,k]  (complex, 3-term hi/lo split)
// CTA tile M=64 (batch) x N=128 (i). 16 warps: 4(M) x 4(N), warp tile 16x32.
// grid (DD/128=32, BB/64=4) = 128 CTAs, 512 threads.
// ---------------------------------------------------------------------------
template <bool CPLX>
__global__ void __launch_bounds__(512, 1)
cgemm_mma(const float* __restrict__ Ur, const float* __restrict__ Ui,
          const float* __restrict__ Sr, const float* __restrict__ Si,
          float* __restrict__ Or, float* __restrict__ Oi) {
    extern __shared__ __align__(16) __nv_bfloat16 sm[];

    const int tid = threadIdx.x;
    const int wid = tid >> 5;
    const int lane = tid & 31;
    const int ibase = blockIdx.x * 128;
    const int bbase = blockIdx.y * 64;

    // ---- loader mapping: 512 threads, each stages 3 float4 per chunk ----
    const int arow = tid >> 2;            // 0..127
    const int akp = (tid & 3) << 2;       // 0,4,8,12
    // S pass: rows 0..63 -> Sr, rows 64..127 -> Si
    const int s_is_i = arow >> 6;         // 0 or 1
    const int s_row = arow & 63;
    const float* pS = (s_is_i ? Si : Sr) + (size_t)(bbase + s_row) * DD + akp;
    const float* pUr = Ur + (size_t)(ibase + arow) * DD + akp;
    const float* pUi = Ui + (size_t)(ibase + arow) * DD + akp;
    const int sTileH = s_is_i ? T_SIH : T_SRH;
    const int sTileL = s_is_i ? T_SIL : T_SRL;

    // ---- compute mapping: 4x4 warps, warp tile m16 x n32 ----
    const int warp_m = wid & 3;           // 0..3 (16 rows each)
    const int warp_n = wid >> 2;          // 0..3 (32 cols each)
    const int lrow = lane >> 2;
    const int lcol2 = (lane & 3) << 1;

    const uint32_t aLane = (uint32_t)((lane & 15) * SROWB + (lane >> 4) * 16);
    const uint32_t bLane = (uint32_t)((((lane >> 4) << 3) + (lane & 7)) * SROWB +
                                      ((lane >> 3) & 1) * 16);
    const uint32_t smbase = smem_u32(sm);
    const uint32_t aOff = aLane + (uint32_t)(warp_m * 16 * SROWB);

    float cR[4][4], cI[4][4];
#pragma unroll
    for (int n = 0; n < 4; ++n)
#pragma unroll
        for (int r = 0; r < 4; ++r) { cR[n][r] = 0.f; cI[n][r] = 0.f; }

    auto stage = [&](int buf, float4 s, float4 ur, float4 ui) {
        __nv_bfloat16* B = sm + buf * BUF_ELEMS;
        store_hilo(B + sTileH * SROW, B + sTileL * SROW, s_row, akp, s);
        store_hilo(B + T_URH * SROW, B + T_URL * SROW, arow, akp, ur);
        store_hilo(B + T_UIH * SROW, B + T_UIL * SROW, arow, akp, ui);
    };

    // prologue
    float4 v_s = *reinterpret_cast<const float4*>(pS);
    float4 v_ur = *reinterpret_cast<const float4*>(pUr);
    float4 v_ui = *reinterpret_cast<const float4*>(pUi);
    stage(0, v_s, v_ur, v_ui);
    v_s = *reinterpret_cast<const float4*>(pS + KC);
    v_ur = *reinterpret_cast<const float4*>(pUr + KC);
    v_ui = *reinterpret_cast<const float4*>(pUi + KC);
    __syncthreads();

#pragma unroll 1
    for (int c = 0; c < NCHUNK; ++c) {
        if (c + 1 < NCHUNK) stage((c + 1) & 1, v_s, v_ur, v_ui);
        if (c + 2 < NCHUNK) {
            const int off = (c + 2) * KC;
            v_s = *reinterpret_cast<const float4*>(pS + off);
            v_ur = *reinterpret_cast<const float4*>(pUr + off);
            v_ui = *reinterpret_cast<const float4*>(pUi + off);
        }

        const uint32_t base = smbase + (uint32_t)((c & 1) * BUF_ELEMS * 2);
        // A fragments (m16 x k16)
        uint32_t aSrH[4], aSrL[4], aSiH[4], aSiL[4], aSiHn[4], aSiLn[4];
        ldm4(aSrH, base + aOff + T_SRH * SROWB);
        ldm4(aSrL, base + aOff + T_SRL * SROWB);
        if (CPLX) {
            ldm4(aSiH, base + aOff + T_SIH * SROWB);
            ldm4(aSiL, base + aOff + T_SIL * SROWB);
#pragma unroll
            for (int r = 0; r < 4; ++r) {
                aSiHn[r] = aSiH[r] ^ 0x80008000u;
                aSiLn[r] = aSiL[r] ^ 0x80008000u;
            }
        }
#pragma unroll
        for (int np = 0; np < 2; ++np) {
            const uint32_t bm = base + bLane + (uint32_t)((warp_n * 32 + np * 16) * SROWB);
            uint32_t bUrH[4], bUrL[4], bUiH[4], bUiL[4];
            ldm4(bUrH, bm + T_URH * SROWB);
            ldm4(bUrL, bm + T_URL * SROWB);
            ldm4(bUiH, bm + T_UIH * SROWB);
            ldm4(bUiL, bm + T_UIL * SROWB);
            const int n0 = np * 2, n1 = np * 2 + 1;
            // C_R += Sr*Ur
            MMA(cR[n0], aSrH, bUrH + 0);
            MMA(cR[n0], aSrL, bUrH + 0);
            MMA(cR[n0], aSrH, bUrL + 0);
            MMA(cR[n1], aSrH, bUrH + 2);
            MMA(cR[n1], aSrL, bUrH + 2);
            MMA(cR[n1], aSrH, bUrL + 2);
            // C_I += Sr*Ui
            MMA(cI[n0], aSrH, bUiH + 0);
            MMA(cI[n0], aSrL, bUiH + 0);
            MMA(cI[n0], aSrH, bUiL + 0);
            MMA(cI[n1], aSrH, bUiH + 2);
            MMA(cI[n1], aSrL, bUiH + 2);
            MMA(cI[n1], aSrH, bUiL + 2);
            if (CPLX) {
                // C_R -= Si*Ui
                MMA(cR[n0], aSiHn, bUiH + 0);
                MMA(cR[n0], aSiLn, bUiH + 0);
                MMA(cR[n0], aSiHn, bUiL + 0);
                MMA(cR[n1], aSiHn, bUiH + 2);
                MMA(cR[n1], aSiLn, bUiH + 2);
                MMA(cR[n1], aSiHn, bUiL + 2);
                // C_I += Si*Ur
                MMA(cI[n0], aSiH, bUrH + 0);
                MMA(cI[n0], aSiL, bUrH + 0);
                MMA(cI[n0], aSiH, bUrL + 0);
                MMA(cI[n1], aSiH, bUrH + 2);
                MMA(cI[n1], aSiL, bUrH + 2);
                MMA(cI[n1], aSiH, bUrL + 2);
            }
        }
        __syncthreads();
    }

    // epilogue: (B, D) row-major, coalesced float2 per fragment pair
#pragma unroll
    for (int n = 0; n < 4; ++n) {
        const int brow = bbase + warp_m * 16 + lrow;
        const int icol = ibase + warp_n * 32 + n * 8 + lcol2;
        *reinterpret_cast<float2*>(Or + (size_t)brow * DD + icol) =
            make_float2(cR[n][0], cR[n][1]);
        *reinterpret_cast<float2*>(Or + (size_t)(brow + 8) * DD + icol) =
            make_float2(cR[n][2], cR[n][3]);
        *reinterpret_cast<float2*>(Oi + (size_t)brow * DD + icol) =
            make_float2(cI[n][0], cI[n][1]);
        *reinterpret_cast<float2*>(Oi + (size_t)(brow + 8) * DD + icol) =
            make_float2(cI[n][2], cI[n][3]);
    }
}

// ---------------------------------------------------------------------------
__global__ void normalize_kernel(const float* __restrict__ x, float* __restrict__ sr) {
    const int b = blockIdx.x;
    const float4* xv = reinterpret_cast<const float4*>(x + (size_t)b * DD);
    float ss = 0.f;
#pragma unroll 4
    for (int i = threadIdx.x; i < DD / 4; i += blockDim.x) {
        float4 v = xv[i];
        ss += v.x * v.x + v.y * v.y + v.z * v.z + v.w * v.w;
    }
    __shared__ float red[256];
    red[threadIdx.x] = ss;
    __syncthreads();
    for (int s = 128; s > 0; s >>= 1) {
        if (threadIdx.x < s) red[threadIdx.x] += red[threadIdx.x + s];
        __syncthreads();
    }
    const float inv = rsqrtf(red[0]);
    float4* ov = reinterpret_cast<float4*>(sr + (size_t)b * DD);
    for (int i = threadIdx.x; i < DD / 4; i += blockDim.x) {
        float4 v = xv[i];
        v.x *= inv; v.y *= inv; v.z *= inv; v.w *= inv;
        ov[i] = v;
    }
}

__global__ void perm_kernel(const float* __restrict__ inr, const float* __restrict__ ini,
                            float* __restrict__ outr, float* __restrict__ outi) {
    const int idx = blockIdx.x * blockDim.x + threadIdx.x;
    const int b = idx >> 12;
    const int j = idx & (DD - 1);
    int m = j;
#pragma unroll
    for (int i = NW - 1; i >= 0; --i) {
        const int cc = NW - 1 - i;
        const int t = NW - 1 - ((i + 1) % NW);
        m ^= ((m >> cc) & 1) << t;
    }
    const size_t src = ((size_t)b << 12) + m;
    outr[idx] = inr[src];
    outi[idx] = ini[src];
}

__global__ void abs_kernel(const float* __restrict__ re, const float* __restrict__ im,
                           float* __restrict__ out) {
    const int idx = blockIdx.x * blockDim.x + threadIdx.x;
    const float r = re[idx];
    const float i = im[idx];
    out[idx] = sqrtf(r * r + i * i);
}

// ---------------------------------------------------------------------------
extern "C" void kernel_launch(void* const* d_in, const int* in_sizes, int n_in,
                              void* d_out, int out_size) {
    const float* x   = (const float*)d_in[0];
    const float* u0r = (const float*)d_in[1];
    const float* u0i = (const float*)d_in[2];
    const float* u1r = (const float*)d_in[3];
    const float* u1i = (const float*)d_in[4];
    const float* u2r = (const float*)d_in[5];
    const float* u2i = (const float*)d_in[6];
    const float* u3r = (const float*)d_in[7];
    const float* u3i = (const float*)d_in[8];
    float* out = (float*)d_out;

    cudaFuncSetAttribute(cgemm_mma<true>, cudaFuncAttributeMaxDynamicSharedMemorySize,
                         SMEM_BYTES);
    cudaFuncSetAttribute(cgemm_mma<false>, cudaFuncAttributeMaxDynamicSharedMemorySize,
                         SMEM_BYTES);

    float *r0, *i0, *r1, *i1;
    cudaGetSymbolAddress((void**)&r0, g_r0);
    cudaGetSymbolAddress((void**)&i0, g_i0);
    cudaGetSymbolAddress((void**)&r1, g_r1);
    cudaGetSymbolAddress((void**)&i1, g_i1);

    const dim3 gg(DD / 128, BB / 64);  // (32, 4) = 128 CTAs
    const int elems = BB * DD;

    normalize_kernel<<<BB, 256>>>(x, r0);
    cgemm_mma<false><<<gg, 512, SMEM_BYTES>>>(u0r, u0i, r0, r0, r1, i1);
    perm_kernel<<<elems / 256, 256>>>(r1, i1, r0, i0);
    cgemm_mma<true><<<gg, 512, SMEM_BYTES>>>(u1r, u1i, r0, i0, r1, i1);
    cgemm_mma<true><<<gg, 512, SMEM_BYTES>>>(u2r, u2i, r1, i1, r0, i0);
    perm_kernel<<<elems / 256, 256>>>(r0, i0, r1, i1);
    cgemm_mma<true><<<gg, 512, SMEM_BYTES>>>(u3r, u3i, r1, i1, r0, i0);
    abs_kernel<<<elems / 256, 256>>>(r0, i0, out);
}